// round 9
// baseline (speedup 1.0000x reference)
#include <cuda_runtime.h>
#include <cstdint>

#define T_TOK 4096
#define H_DIM 2048
#define I_DIM 1408
#define E_NUM 16
#define MAXPE 4096
#define NASSIGN (T_TOK * 2)
#define SMS 136            // smem k-row stride in floats

// ---------------- device scratch ----------------
__device__ int   g_counts[E_NUM];
__device__ int   g_off[E_NUM + 1];
__device__ int   g_tok[E_NUM * MAXPE];
__device__ float g_wt [E_NUM * MAXPE];
__device__ int   g_slot[T_TOK * 2];
__device__ float g_hbuf[(size_t)NASSIGN * I_DIM];   // 46 MB
__device__ float g_obuf[(size_t)NASSIGN * H_DIM];   // 64 MB

// ---------------- helpers ----------------
__device__ __forceinline__ float4 cvt4(float4 v) {   // fp32 -> tf32 (round-to-nearest)
    asm("cvt.rna.tf32.f32 %0, %0;" : "+f"(v.x));
    asm("cvt.rna.tf32.f32 %0, %0;" : "+f"(v.y));
    asm("cvt.rna.tf32.f32 %0, %0;" : "+f"(v.z));
    asm("cvt.rna.tf32.f32 %0, %0;" : "+f"(v.w));
    return v;
}
__device__ __forceinline__ float silu_f(float g) { return g / (1.f + __expf(-g)); }

__device__ __forceinline__ void mma_tf32(float* c, const uint32_t* a,
                                         uint32_t b0, uint32_t b1) {
    asm volatile(
        "mma.sync.aligned.m16n8k8.row.col.f32.tf32.tf32.f32 "
        "{%0,%1,%2,%3}, {%4,%5,%6,%7}, {%8,%9}, {%0,%1,%2,%3};"
        : "+f"(c[0]), "+f"(c[1]), "+f"(c[2]), "+f"(c[3])
        : "r"(a[0]), "r"(a[1]), "r"(a[2]), "r"(a[3]), "r"(b0), "r"(b1));
}

// ---------------- kernel 0: zero counters ----------------
__global__ void zero_counts_kernel() {
    if (threadIdx.x < E_NUM) g_counts[threadIdx.x] = 0;
}

// ---------------- kernel 1: router ----------------
__global__ void router_kernel(const float* __restrict__ x, const float* __restrict__ gw) {
    __shared__ float xs[H_DIM];
    __shared__ float logits[E_NUM];
    const int t = blockIdx.x;
    const float* xr = x + (size_t)t * H_DIM;
    for (int i = threadIdx.x; i < H_DIM; i += 256) xs[i] = xr[i];
    __syncthreads();

    const int w = threadIdx.x >> 5;
    const int lane = threadIdx.x & 31;
    const int e0 = w * 2;
    float s0 = 0.f, s1 = 0.f;
    const float* g0 = gw + (size_t)e0 * H_DIM;
    const float* g1 = g0 + H_DIM;
    for (int k = lane; k < H_DIM; k += 32) {
        float xv = xs[k];
        s0 += xv * g0[k];
        s1 += xv * g1[k];
    }
    #pragma unroll
    for (int o = 16; o; o >>= 1) {
        s0 += __shfl_xor_sync(0xFFFFFFFFu, s0, o);
        s1 += __shfl_xor_sync(0xFFFFFFFFu, s1, o);
    }
    if (lane == 0) { logits[e0] = s0; logits[e0 + 1] = s1; }
    __syncthreads();

    if (threadIdx.x == 0) {
        int b0 = 0, b1 = -1;
        float l0 = -1e30f, l1 = -1e30f;
        #pragma unroll
        for (int e = 0; e < E_NUM; e++) {
            float l = logits[e];
            if (l > l0) { l1 = l0; b1 = b0; l0 = l; b0 = e; }
            else if (l > l1) { l1 = l; b1 = e; }
        }
        float p1 = __expf(l1 - l0);
        float inv = 1.f / (1.f + p1);
        int pos0 = atomicAdd(&g_counts[b0], 1);
        g_tok[b0 * MAXPE + pos0] = t;
        g_wt [b0 * MAXPE + pos0] = inv;
        g_slot[t * 2 + 0] = b0 * MAXPE + pos0;
        int pos1 = atomicAdd(&g_counts[b1], 1);
        g_tok[b1 * MAXPE + pos1] = t;
        g_wt [b1 * MAXPE + pos1] = p1 * inv;
        g_slot[t * 2 + 1] = b1 * MAXPE + pos1;
    }
}

// ---------------- kernel 2: exclusive prefix ----------------
__global__ void prefix_kernel() {
    const int lane = threadIdx.x;
    int v = (lane < E_NUM) ? g_counts[lane] : 0;
    #pragma unroll
    for (int o = 1; o < 32; o <<= 1) {
        int n = __shfl_up_sync(0xFFFFFFFFu, v, o);
        if (lane >= o) v += n;
    }
    if (lane < E_NUM) g_off[lane + 1] = v;
    if (lane == 0)    g_off[0] = 0;
}

// Swizzled smem index for element (k, idx) of a 128-wide tile:
//   addr = k*SMS + ((idx + (k>>2)*8) & 127)
// Stores (4 scalar STS per loader thread) and all mma fragment loads are
// bank-conflict-free under this mapping.

#define STAGE_STORE(AP, BP, s0v, s1v, b0v, b1v, S0, S1, SB0, SB1)            \
    do {                                                                     \
        (AP)[(k4 + 0) * SMS + (S0)] = (s0v).x;                               \
        (AP)[(k4 + 1) * SMS + (S0)] = (s0v).y;                               \
        (AP)[(k4 + 2) * SMS + (S0)] = (s0v).z;                               \
        (AP)[(k4 + 3) * SMS + (S0)] = (s0v).w;                               \
        (AP)[(k4 + 0) * SMS + (S1)] = (s1v).x;                               \
        (AP)[(k4 + 1) * SMS + (S1)] = (s1v).y;                               \
        (AP)[(k4 + 2) * SMS + (S1)] = (s1v).z;                               \
        (AP)[(k4 + 3) * SMS + (S1)] = (s1v).w;                               \
        (BP)[(k4 + 0) * SMS + (SB0)] = (b0v).x;                              \
        (BP)[(k4 + 1) * SMS + (SB0)] = (b0v).y;                              \
        (BP)[(k4 + 2) * SMS + (SB0)] = (b0v).z;                              \
        (BP)[(k4 + 3) * SMS + (SB0)] = (b0v).w;                              \
        (BP)[(k4 + 0) * SMS + (SB1)] = (b1v).x;                              \
        (BP)[(k4 + 1) * SMS + (SB1)] = (b1v).y;                              \
        (BP)[(k4 + 2) * SMS + (SB1)] = (b1v).z;                              \
        (BP)[(k4 + 3) * SMS + (SB1)] = (b1v).w;                              \
    } while (0)

// ---------------- kernel 3: tf32 mma grouped GEMM1 (gate+up) + SwiGLU ----------------
// Block tile M=128 x 64 I-cols (gate cols 0..63 of Bs, up cols 64..127).
// 8 warps: 4m x 2n, warp tile m32 x (gate32|up32). Double-buffered smem.
__global__ __launch_bounds__(256, 2)
void gemm1_mma(const float* __restrict__ x, const float* __restrict__ ws) {
    const int e  = blockIdx.z;
    const int Me = g_counts[e];
    const int m0 = blockIdx.x * 128;
    if (m0 >= Me) return;
    const int n0  = blockIdx.y * 64;
    const int off = g_off[e];

    __shared__ float As[2][16 * SMS];
    __shared__ float Bs[2][16 * SMS];

    const int tid  = threadIdx.x;
    const int lane = tid & 31;
    const int wid  = tid >> 5;
    const int m0w  = (wid >> 1) * 32;
    const int nw   = wid & 1;

    const int r0l = tid >> 2;            // 0..63
    const int r1l = r0l + 64;
    const int k4  = (tid & 3) * 4;
    const int soff = (tid & 3) * 8;
    const int sa0 = (r0l + soff) & 127;
    const int sa1 = (r1l + soff) & 127;
    const int sbg = sa0;                       // gate -> Bs col r0l
    const int sbu = (64 + r0l + soff) & 127;   // up   -> Bs col 64+r0l

    const int tok0 = g_tok[e * MAXPE + min(m0 + r0l, Me - 1)];
    const int tok1 = g_tok[e * MAXPE + min(m0 + r1l, Me - 1)];
    const float* a0p = x + (size_t)tok0 * H_DIM + k4;
    const float* a1p = x + (size_t)tok1 * H_DIM + k4;
    const float* bgp = ws + ((size_t)e * (2 * I_DIM) + (n0 + r0l)) * H_DIM + k4;
    const float* bup = bgp + (size_t)I_DIM * H_DIM;

    float acc[2][8][4];
    #pragma unroll
    for (int i = 0; i < 2; i++)
        #pragma unroll
        for (int j = 0; j < 8; j++)
            #pragma unroll
            for (int q = 0; q < 4; q++) acc[i][j][q] = 0.f;

    const int lc = lane & 3;
    const int lr = lane >> 2;

    // prologue: chunk 0 -> stage 0; prefetch chunk 1 -> regs
    float4 av0 = cvt4(*(const float4*)a0p);
    float4 av1 = cvt4(*(const float4*)a1p);
    float4 gv  = cvt4(*(const float4*)bgp);
    float4 uv  = cvt4(*(const float4*)bup);
    STAGE_STORE(&As[0][0], &Bs[0][0], av0, av1, gv, uv, sa0, sa1, sbg, sbu);
    av0 = cvt4(*(const float4*)(a0p + 16));
    av1 = cvt4(*(const float4*)(a1p + 16));
    gv  = cvt4(*(const float4*)(bgp + 16));
    uv  = cvt4(*(const float4*)(bup + 16));
    __syncthreads();

    const int NIT = H_DIM / 16;   // 128
    #pragma unroll 1
    for (int c = 0; c < NIT; c++) {
        if (c + 1 < NIT) {
            float* An = &As[(c + 1) & 1][0];
            float* Bn = &Bs[(c + 1) & 1][0];
            STAGE_STORE(An, Bn, av0, av1, gv, uv, sa0, sa1, sbg, sbu);
            if (c + 2 < NIT) {
                const int kn = (c + 2) * 16;
                av0 = cvt4(*(const float4*)(a0p + kn));
                av1 = cvt4(*(const float4*)(a1p + kn));
                gv  = cvt4(*(const float4*)(bgp + kn));
                uv  = cvt4(*(const float4*)(bup + kn));
            }
        }
        const float* Ab = &As[c & 1][0];
        const float* Bb = &Bs[c & 1][0];

        #pragma unroll
        for (int kk = 0; kk < 16; kk += 8) {
            const int klo = kk + lc;
            const int khi = kk + lc + 4;
            const int offlo = ((klo >> 2) & 3) * 8;
            const int offhi = ((khi >> 2) & 3) * 8;
            uint32_t a[2][4];
            #pragma unroll
            for (int i = 0; i < 2; i++) {
                const int rb = m0w + i * 16 + lr;
                a[i][0] = __float_as_uint(Ab[klo * SMS + ((rb     + offlo) & 127)]);
                a[i][1] = __float_as_uint(Ab[klo * SMS + ((rb + 8 + offlo) & 127)]);
                a[i][2] = __float_as_uint(Ab[khi * SMS + ((rb     + offhi) & 127)]);
                a[i][3] = __float_as_uint(Ab[khi * SMS + ((rb + 8 + offhi) & 127)]);
            }
            #pragma unroll
            for (int j = 0; j < 8; j++) {
                const int cb = (j < 4) ? (nw * 32 + j * 8) : (64 + nw * 32 + (j - 4) * 8);
                const int cl = cb + lr;
                uint32_t b0 = __float_as_uint(Bb[klo * SMS + ((cl + offlo) & 127)]);
                uint32_t b1 = __float_as_uint(Bb[khi * SMS + ((cl + offhi) & 127)]);
                mma_tf32(acc[0][j], a[0], b0, b1);
                mma_tf32(acc[1][j], a[1], b0, b1);
            }
        }
        __syncthreads();
    }

    // epilogue: SwiGLU (gate frag j pairs with up frag j+4), float2 stores
    #pragma unroll
    for (int i = 0; i < 2; i++) {
        const int row0 = m0 + m0w + i * 16 + lr;
        const int row1 = row0 + 8;
        #pragma unroll
        for (int j = 0; j < 4; j++) {
            const float* g = acc[i][j];
            const float* u = acc[i][j + 4];
            const int col = n0 + nw * 32 + j * 8 + 2 * lc;
            if (row0 < Me) {
                float2 h = { silu_f(g[0]) * u[0], silu_f(g[1]) * u[1] };
                *(float2*)&g_hbuf[(size_t)(off + row0) * I_DIM + col] = h;
            }
            if (row1 < Me) {
                float2 h = { silu_f(g[2]) * u[2], silu_f(g[3]) * u[3] };
                *(float2*)&g_hbuf[(size_t)(off + row1) * I_DIM + col] = h;
            }
        }
    }
}

// ---------------- kernel 4: tf32 mma grouped GEMM2 (down) + weighted store ----------------
// Block tile M=128 x N=128. 8 warps: 4m x 2n, warp tile m32 x n64. Double-buffered.
__global__ __launch_bounds__(256, 2)
void gemm2_mma(const float* __restrict__ w2s) {
    const int e  = blockIdx.z;
    const int Me = g_counts[e];
    const int m0 = blockIdx.x * 128;
    if (m0 >= Me) return;
    const int n0  = blockIdx.y * 128;
    const int off = g_off[e];

    __shared__ float As[2][16 * SMS];
    __shared__ float Bs[2][16 * SMS];

    const int tid  = threadIdx.x;
    const int lane = tid & 31;
    const int wid  = tid >> 5;
    const int m0w  = (wid >> 1) * 32;
    const int nw   = wid & 1;

    const int r0l = tid >> 2;
    const int r1l = r0l + 64;
    const int k4  = (tid & 3) * 4;
    const int soff = (tid & 3) * 8;
    const int sa0 = (r0l + soff) & 127;
    const int sa1 = (r1l + soff) & 127;

    const int cr0 = min(m0 + r0l, Me - 1);
    const int cr1 = min(m0 + r1l, Me - 1);
    const float* a0p = g_hbuf + (size_t)(off + cr0) * I_DIM + k4;
    const float* a1p = g_hbuf + (size_t)(off + cr1) * I_DIM + k4;
    const float* b0p = w2s + ((size_t)e * H_DIM + (n0 + r0l)) * I_DIM + k4;
    const float* b1p = w2s + ((size_t)e * H_DIM + (n0 + r1l)) * I_DIM + k4;

    float acc[2][8][4];
    #pragma unroll
    for (int i = 0; i < 2; i++)
        #pragma unroll
        for (int j = 0; j < 8; j++)
            #pragma unroll
            for (int q = 0; q < 4; q++) acc[i][j][q] = 0.f;

    const int lc = lane & 3;
    const int lr = lane >> 2;

    // prologue
    float4 av0 = cvt4(*(const float4*)a0p);
    float4 av1 = cvt4(*(const float4*)a1p);
    float4 bv0 = cvt4(*(const float4*)b0p);
    float4 bv1 = cvt4(*(const float4*)b1p);
    STAGE_STORE(&As[0][0], &Bs[0][0], av0, av1, bv0, bv1, sa0, sa1, sa0, sa1);
    av0 = cvt4(*(const float4*)(a0p + 16));
    av1 = cvt4(*(const float4*)(a1p + 16));
    bv0 = cvt4(*(const float4*)(b0p + 16));
    bv1 = cvt4(*(const float4*)(b1p + 16));
    __syncthreads();

    const int NIT = I_DIM / 16;   // 88
    #pragma unroll 1
    for (int c = 0; c < NIT; c++) {
        if (c + 1 < NIT) {
            float* An = &As[(c + 1) & 1][0];
            float* Bn = &Bs[(c + 1) & 1][0];
            STAGE_STORE(An, Bn, av0, av1, bv0, bv1, sa0, sa1, sa0, sa1);
            if (c + 2 < NIT) {
                const int kn = (c + 2) * 16;
                av0 = cvt4(*(const float4*)(a0p + kn));
                av1 = cvt4(*(const float4*)(a1p + kn));
                bv0 = cvt4(*(const float4*)(b0p + kn));
                bv1 = cvt4(*(const float4*)(b1p + kn));
            }
        }
        const float* Ab = &As[c & 1][0];
        const float* Bb = &Bs[c & 1][0];

        #pragma unroll
        for (int kk = 0; kk < 16; kk += 8) {
            const int klo = kk + lc;
            const int khi = kk + lc + 4;
            const int offlo = ((klo >> 2) & 3) * 8;
            const int offhi = ((khi >> 2) & 3) * 8;
            uint32_t a[2][4];
            #pragma unroll
            for (int i = 0; i < 2; i++) {
                const int rb = m0w + i * 16 + lr;
                a[i][0] = __float_as_uint(Ab[klo * SMS + ((rb     + offlo) & 127)]);
                a[i][1] = __float_as_uint(Ab[klo * SMS + ((rb + 8 + offlo) & 127)]);
                a[i][2] = __float_as_uint(Ab[khi * SMS + ((rb     + offhi) & 127)]);
                a[i][3] = __float_as_uint(Ab[khi * SMS + ((rb + 8 + offhi) & 127)]);
            }
            #pragma unroll
            for (int j = 0; j < 8; j++) {
                const int cl = nw * 64 + j * 8 + lr;
                uint32_t b0 = __float_as_uint(Bb[klo * SMS + ((cl + offlo) & 127)]);
                uint32_t b1 = __float_as_uint(Bb[khi * SMS + ((cl + offhi) & 127)]);
                mma_tf32(acc[0][j], a[0], b0, b1);
                mma_tf32(acc[1][j], a[1], b0, b1);
            }
        }
        __syncthreads();
    }

    // epilogue: weighted partials into g_obuf (no atomics)
    #pragma unroll
    for (int i = 0; i < 2; i++) {
        const int row0 = m0 + m0w + i * 16 + lr;
        const int row1 = row0 + 8;
        float wt0 = (row0 < Me) ? g_wt[e * MAXPE + row0] : 0.f;
        float wt1 = (row1 < Me) ? g_wt[e * MAXPE + row1] : 0.f;
        #pragma unroll
        for (int j = 0; j < 8; j++) {
            const int col = n0 + nw * 64 + j * 8 + 2 * lc;
            const float* c = acc[i][j];
            if (row0 < Me) {
                float2 o = { wt0 * c[0], wt0 * c[1] };
                *(float2*)&g_obuf[(size_t)(off + row0) * H_DIM + col] = o;
            }
            if (row1 < Me) {
                float2 o = { wt1 * c[2], wt1 * c[3] };
                *(float2*)&g_obuf[(size_t)(off + row1) * H_DIM + col] = o;
            }
        }
    }
}

// ---------------- kernel 5: combine two expert partials per token ----------------
__global__ void combine_kernel(float* __restrict__ out) {
    const int t = blockIdx.x;
    const int s0 = g_slot[t * 2 + 0];
    const int s1 = g_slot[t * 2 + 1];
    const int r0 = g_off[s0 >> 12] + (s0 & (MAXPE - 1));
    const int r1 = g_off[s1 >> 12] + (s1 & (MAXPE - 1));
    const float4* p0 = (const float4*)(g_obuf + (size_t)r0 * H_DIM);
    const float4* p1 = (const float4*)(g_obuf + (size_t)r1 * H_DIM);
    float4* po = (float4*)(out + (size_t)t * H_DIM);
    for (int i = threadIdx.x; i < H_DIM / 4; i += 256) {
        float4 a = p0[i], b = p1[i];
        float4 o = {a.x + b.x, a.y + b.y, a.z + b.z, a.w + b.w};
        po[i] = o;
    }
}

// ---------------- launch ----------------
extern "C" void kernel_launch(void* const* d_in, const int* in_sizes, int n_in,
                              void* d_out, int out_size) {
    const float* x   = (const float*)d_in[0];
    const float* gw  = (const float*)d_in[1];
    const float* ws  = (const float*)d_in[2];
    const float* w2s = (const float*)d_in[3];
    float* out = (float*)d_out;

    zero_counts_kernel<<<1, 32>>>();
    router_kernel<<<T_TOK, 256>>>(x, gw);
    prefix_kernel<<<1, 32>>>();
    gemm1_mma<<<dim3(MAXPE / 128, I_DIM / 64, E_NUM), 256>>>(x, ws);
    gemm2_mma<<<dim3(MAXPE / 128, H_DIM / 128, E_NUM), 256>>>(w2s);
    combine_kernel<<<T_TOK, 256>>>(out);
}